// round 2
// baseline (speedup 1.0000x reference)
#include <cuda_runtime.h>
#include <cstdint>
#include <cstddef>

#define B_    256
#define N_    256
#define L_    1024
#define D_    256
#define KQ_   64
#define OUT_  64

// ---------------- scratch (device globals: allocation-free rule) -------------
__device__ float g_q[B_ * KQ_];                         // scaled q projections
__device__ float g_k[(size_t)N_ * L_ * KQ_];            // 64 MB
__device__ float g_v[(size_t)N_ * L_ * OUT_];           // 64 MB

using ull = unsigned long long;

// packed fp32x2 helpers (sm_103a fma.rn.f32x2 — 2x fp32 FMA throughput)
__device__ __forceinline__ ull pk2(float x, float y) {
    ull r; asm("mov.b64 %0, {%1, %2};" : "=l"(r) : "f"(x), "f"(y)); return r;
}
__device__ __forceinline__ void fma2(ull& a, ull b, ull c) {
    asm("fma.rn.f32x2 %0, %1, %2, %0;" : "+l"(a) : "l"(b), "l"(c));
}
__device__ __forceinline__ float2 up2(ull v) {
    float2 r; asm("mov.b64 {%0, %1}, %2;" : "=f"(r.x), "=f"(r.y) : "l"(v)); return r;
}
__device__ __forceinline__ float hsum2(ull v) { float2 p = up2(v); return p.x + p.y; }

// ---------------- kernel 1: q = 0.125 * queries @ Wq -------------------------
__global__ void proj_q_kernel(const float* __restrict__ queries,
                              const float* __restrict__ Wq) {
    __shared__ float srow[D_];
    int b = blockIdx.x, j = threadIdx.x;
    for (int d = j; d < D_; d += 64) srow[d] = queries[b * D_ + d];
    __syncthreads();
    float acc = 0.f;
#pragma unroll 8
    for (int d = 0; d < D_; d++) acc = fmaf(srow[d], Wq[d * KQ_ + j], acc);
    g_q[b * KQ_ + j] = acc * 0.125f;   // fold 1/sqrt(KQ) into q
}

// ---------------- kernel 2: k = keys@Wk, v = values@Wv (rows-tiled GEMM) -----
#define PROJ_ROWS 128
#define INPAD     258   // 4-row stride = 1032 floats ≡ 8 mod 32 banks: conflict-free

__global__ __launch_bounds__(256, 1)
void proj_kernel(const float* __restrict__ keys, const float* __restrict__ values,
                 const float* __restrict__ Wk, const float* __restrict__ Wv) {
    extern __shared__ float sm[];
    float* sW  = sm;                 // 256*64 = 16384 floats
    float* sIn = sm + D_ * KQ_;      // 128*258 floats

    const float* in; const float* W; float* out;
    if (blockIdx.y == 0) { in = keys;   W = Wk; out = g_k; }
    else                 { in = values; W = Wv; out = g_v; }

    int tid = threadIdx.x;

    // load full weight matrix to SMEM (float4 coalesced)
    const float4* W4 = (const float4*)W;
    float4* sW4 = (float4*)sW;
    for (int m = tid; m < (D_ * KQ_) / 4; m += 256) sW4[m] = W4[m];

    // load 128-row input tile (float4 gmem, float2 SMEM stores to honor pad 258)
    size_t rowbase = (size_t)blockIdx.x * PROJ_ROWS;
    const float4* in4 = (const float4*)(in + rowbase * D_);
    for (int m = tid; m < PROJ_ROWS * D_ / 4; m += 256) {
        int row = m >> 6, f = m & 63;
        float4 v = in4[m];
        float* dst = sIn + row * INPAD + (f << 2);
        *(float2*)dst       = make_float2(v.x, v.y);
        *(float2*)(dst + 2) = make_float2(v.z, v.w);
    }
    __syncthreads();

    int tx = tid & 7, ty = tid >> 3;
    int r0 = ty << 2;                 // 4 rows per thread
    // 8 cols per thread (tx*8..tx*8+7) as 4 packed f32x2 accumulators per row
    ull acc[4][4];
#pragma unroll
    for (int i = 0; i < 4; i++)
#pragma unroll
        for (int c = 0; c < 4; c++) acc[i][c] = 0ull;

#pragma unroll 4
    for (int d = 0; d < D_; d++) {
        float a0 = sIn[(r0 + 0) * INPAD + d];
        float a1 = sIn[(r0 + 1) * INPAD + d];
        float a2 = sIn[(r0 + 2) * INPAD + d];
        float a3 = sIn[(r0 + 3) * INPAD + d];
        ull p0 = pk2(a0, a0), p1 = pk2(a1, a1), p2 = pk2(a2, a2), p3 = pk2(a3, a3);
        const float* wr = sW + d * KQ_ + (tx << 3);
        ulonglong2 b01 = *(const ulonglong2*)(wr);
        ulonglong2 b23 = *(const ulonglong2*)(wr + 4);
        fma2(acc[0][0], p0, b01.x); fma2(acc[0][1], p0, b01.y);
        fma2(acc[0][2], p0, b23.x); fma2(acc[0][3], p0, b23.y);
        fma2(acc[1][0], p1, b01.x); fma2(acc[1][1], p1, b01.y);
        fma2(acc[1][2], p1, b23.x); fma2(acc[1][3], p1, b23.y);
        fma2(acc[2][0], p2, b01.x); fma2(acc[2][1], p2, b01.y);
        fma2(acc[2][2], p2, b23.x); fma2(acc[2][3], p2, b23.y);
        fma2(acc[3][0], p3, b01.x); fma2(acc[3][1], p3, b01.y);
        fma2(acc[3][2], p3, b23.x); fma2(acc[3][3], p3, b23.y);
    }

#pragma unroll
    for (int i = 0; i < 4; i++) {
        float2 p0 = up2(acc[i][0]), p1 = up2(acc[i][1]);
        float2 p2 = up2(acc[i][2]), p3 = up2(acc[i][3]);
        float* op = out + (rowbase + r0 + i) * (size_t)KQ_ + (tx << 3);
        *(float4*)op       = make_float4(p0.x, p0.y, p1.x, p1.y);
        *(float4*)(op + 4) = make_float4(p2.x, p2.y, p3.x, p3.y);
    }
}

// ------------- kernel 3: fused logits + softmax + attn + attn@v --------------
// block = (n, 32 b-rows). s-tile [32][1024] stays in SMEM (fp32).
#define ROWS_C 32
#define SSTR   1032   // row stride ≡ 8 mod 32 banks
#define KPAD   68     // k/v chunk row stride: Δtx=1 row → 68 ≡ 4 banks, 16B-aligned

__global__ __launch_bounds__(256, 1)
void attn_kernel(float* __restrict__ resOut, float* __restrict__ attnOut) {
    extern __shared__ float sm[];
    float* sS  = sm;                   // 32*1032 floats
    float* sKV = sm + ROWS_C * SSTR;   // 256*68 floats (k chunk, reused for v)

    int n   = blockIdx.y;
    int b0  = blockIdx.x * ROWS_C;
    int tid = threadIdx.x;
    int tx  = tid & 7, ty = tid >> 3;  // warp = 4 rows x 8 lane-groups
    int b   = b0 + ty;

    // q row (scaled) packed into 32 f32x2 registers
    ull q2[32];
    const float2* qp = (const float2*)(g_q + b * KQ_);
#pragma unroll
    for (int j = 0; j < 32; j++) { float2 t = qp[j]; q2[j] = pk2(t.x, t.y); }

    float vmax = -3.402823466e38f;
    float* srow = sS + ty * SSTR;

    // ---- phase 1: s = q . k^T over L in 4 chunks of 256 ----
    for (int ch = 0; ch < 4; ch++) {
        int lbase = ch << 8;
        __syncthreads();
        const float4* g4 = (const float4*)(g_k + ((size_t)n * L_ + lbase) * KQ_);
        for (int m = tid; m < 4096; m += 256) {
            int row = m >> 4, f = m & 15;
            *(float4*)(sKV + row * KPAD + (f << 2)) = g4[m];
        }
        __syncthreads();
#pragma unroll 1
        for (int li = 0; li < 32; li++) {
            int lloc = tx + (li << 3);
            const float* kr = sKV + lloc * KPAD;
            ull a0 = 0, a1 = 0, a2 = 0, a3 = 0;   // 4 chains for ILP
#pragma unroll
            for (int j = 0; j < 32; j += 4) {
                ulonglong2 kA = *(const ulonglong2*)(kr + (j << 1));
                ulonglong2 kB = *(const ulonglong2*)(kr + (j << 1) + 4);
                fma2(a0, q2[j],     kA.x);
                fma2(a1, q2[j + 1], kA.y);
                fma2(a2, q2[j + 2], kB.x);
                fma2(a3, q2[j + 3], kB.y);
            }
            float s = (hsum2(a0) + hsum2(a1)) + (hsum2(a2) + hsum2(a3));
            vmax = fmaxf(vmax, s);
            srow[lbase + lloc] = s;
        }
    }

    // ---- phase 2: softmax (each thread touches only its own row slots) ----
    float m = vmax;
    m = fmaxf(m, __shfl_xor_sync(0xffffffffu, m, 1));
    m = fmaxf(m, __shfl_xor_sync(0xffffffffu, m, 2));
    m = fmaxf(m, __shfl_xor_sync(0xffffffffu, m, 4));
    float ssum = 0.f;
#pragma unroll 4
    for (int li = 0; li < 128; li++) {
        int l = tx + (li << 3);
        float e = __expf(srow[l] - m);
        srow[l] = e;
        ssum += e;
    }
    ssum += __shfl_xor_sync(0xffffffffu, ssum, 1);
    ssum += __shfl_xor_sync(0xffffffffu, ssum, 2);
    ssum += __shfl_xor_sync(0xffffffffu, ssum, 4);
    float inv = 1.0f / ssum;

    size_t aoff = ((size_t)n * B_ + b) * L_;
#pragma unroll 4
    for (int li = 0; li < 128; li++) {
        int l = tx + (li << 3);
        attnOut[aoff + l] = srow[l] * inv;   // normalized attention out
    }

    // ---- phase 3: result[b][n][:] = (e @ v[n]) * inv ----
    ull o0 = 0, o1 = 0, o2 = 0, o3 = 0;      // 8 out cols as 4 f32x2
    for (int ch = 0; ch < 4; ch++) {
        int lbase = ch << 8;
        __syncthreads();                      // everyone past phase 1/2 before sKV reuse
        const float4* g4 = (const float4*)(g_v + ((size_t)n * L_ + lbase) * OUT_);
        for (int mm = tid; mm < 4096; mm += 256) {
            int row = mm >> 4, f = mm & 15;
            *(float4*)(sKV + row * KPAD + (f << 2)) = g4[mm];
        }
        __syncthreads();
        const float* ebase = srow + lbase;
#pragma unroll 4
        for (int lloc = 0; lloc < 256; lloc++) {
            float e = ebase[lloc];
            ull e2 = pk2(e, e);
            const float* vr = sKV + lloc * KPAD + (tx << 3);
            ulonglong2 vA = *(const ulonglong2*)(vr);
            ulonglong2 vB = *(const ulonglong2*)(vr + 4);
            fma2(o0, e2, vA.x); fma2(o1, e2, vA.y);
            fma2(o2, e2, vB.x); fma2(o3, e2, vB.y);
        }
    }

    float2 p0 = up2(o0), p1 = up2(o1), p2 = up2(o2), p3 = up2(o3);
    float* op = resOut + ((size_t)b * N_ + n) * OUT_ + (tx << 3);
    *(float4*)op       = make_float4(p0.x * inv, p0.y * inv, p1.x * inv, p1.y * inv);
    *(float4*)(op + 4) = make_float4(p2.x * inv, p2.y * inv, p3.x * inv, p3.y * inv);
}

// ----------------------------- launcher --------------------------------------
extern "C" void kernel_launch(void* const* d_in, const int* in_sizes, int n_in,
                              void* d_out, int out_size) {
    const float* queries = (const float*)d_in[0];
    const float* keys    = (const float*)d_in[1];
    const float* values  = (const float*)d_in[2];
    const float* Wq      = (const float*)d_in[3];
    const float* Wk      = (const float*)d_in[4];
    const float* Wv      = (const float*)d_in[5];

    float* resOut  = (float*)d_out;                         // [B, N, OUT]
    float* attnOut = resOut + (size_t)B_ * N_ * OUT_;       // [N, B, L]

    const int SMEM_PROJ = (int)((D_ * KQ_ + PROJ_ROWS * INPAD) * sizeof(float));  // ~193 KB
    const int SMEM_ATTN = (int)((ROWS_C * SSTR + 256 * KPAD) * sizeof(float));    // ~197 KB
    cudaFuncSetAttribute(proj_kernel, cudaFuncAttributeMaxDynamicSharedMemorySize, SMEM_PROJ);
    cudaFuncSetAttribute(attn_kernel, cudaFuncAttributeMaxDynamicSharedMemorySize, SMEM_ATTN);

    proj_q_kernel<<<B_, 64>>>(queries, Wq);
    proj_kernel<<<dim3((N_ * L_) / PROJ_ROWS, 2), 256, SMEM_PROJ>>>(keys, values, Wk, Wv);
    attn_kernel<<<dim3(B_ / ROWS_C, N_), 256, SMEM_ATTN>>>(resOut, attnOut);
}